// round 15
// baseline (speedup 1.0000x reference)
#include <cuda_runtime.h>
#include <math.h>

namespace {

constexpr int B = 128;
constexpr int N = 2048;
constexpr int E = 32768;
constexpr int BN = B * N;
constexpr int SPLIT = 8;                   // blocks per batch for edge scans
constexpr int CHUNK = E / SPLIT;           // 4096 edges per block
constexpr int LIST_CAP = 384;              // layer-1 edges per output node
constexpr int NODE_CAP = 800;              // marked nodes per batch (~34 typical)
constexpr float INV_SQRT_DH = 0.7071067811865476f;

// Scratch (device globals — no allocations allowed)
__device__ unsigned g_bitmap[B * 64];                  // needed-node bitmap
__device__ int      g_cnt[B * 2];                      // layer-1 list counters
__device__ int      g_ncnt[B];                         // marked-node counters
__device__ int      g_nodelist[B * NODE_CAP];          // compact marked nodes
__device__ float    g_acc[(size_t)BN * 8];             // [agg0..3 | s0 s1 | pad2]
__device__ int2     g_list[(size_t)B * 2 * LIST_CAP];  // layer-1 edge lists

// ---------------------------------------------------------------------------
// Zero: reset bitmap + counters; pre-mark output nodes, zero their acc,
// seed the node list with them.
// ---------------------------------------------------------------------------
__global__ void __launch_bounds__(64) zero_kernel(
        const int* __restrict__ src_index,
        const int* __restrict__ dst_index) {
    int b = blockIdx.x, t = threadIdx.x;
    g_bitmap[b * 64 + t] = 0u;
    __syncthreads();
    if (t == 0) {
        g_cnt[b * 2 + 0] = 0;
        g_cnt[b * 2 + 1] = 0;
        int out0 = src_index[b];
        int out1 = dst_index[b];
        unsigned* bm = g_bitmap + b * 64;
        bm[out0 >> 5] |= 1u << (out0 & 31);
        bm[out1 >> 5] |= 1u << (out1 & 31);
        float4* acc4 = reinterpret_cast<float4*>(g_acc) + (size_t)b * N * 2;
        float4 z = make_float4(0.f, 0.f, 0.f, 0.f);
        acc4[out0 * 2 + 0] = z; acc4[out0 * 2 + 1] = z;
        acc4[out1 * 2 + 0] = z; acc4[out1 * 2 + 1] = z;
        int* nl = g_nodelist + b * NODE_CAP;
        nl[0] = out0;
        int cnt = 1;
        if (out1 != out0) { nl[1] = out1; cnt = 2; }
        g_ncnt[b] = cnt;
    }
}

// ---------------------------------------------------------------------------
// Mark: stream dst column; edges into output nodes mark src in the bitmap.
// The unique 0->1 marker zeroes that node's acc and appends it to the
// compact node list. B*SPLIT blocks x 256 threads.
// ---------------------------------------------------------------------------
__global__ void __launch_bounds__(256) mark_kernel(
        const int* __restrict__ edge_index,
        const int* __restrict__ src_index,
        const int* __restrict__ dst_index) {
    int blk = blockIdx.x;
    int b = blk >> 3, chunk = blk & 7;
    int out0 = __ldg(src_index + b);
    int out1 = __ldg(dst_index + b);
    const int* ei = edge_index + (size_t)b * 2 * E;
    const int* srcp = ei + chunk * CHUNK;
    const int4* dst4 = reinterpret_cast<const int4*>(ei + E + chunk * CHUNK);
    unsigned* bm = g_bitmap + b * 64;
    float4* acc4 = reinterpret_cast<float4*>(g_acc) + (size_t)b * N * 2;

    for (int i = threadIdx.x; i < CHUNK / 4; i += 256) {
        int4 d = __ldg(dst4 + i);
        int dd[4] = {d.x, d.y, d.z, d.w};
#pragma unroll
        for (int u = 0; u < 4; u++) {
            if (dd[u] == out0 || dd[u] == out1) {
                int s = __ldg(srcp + i * 4 + u);
                unsigned bit = 1u << (s & 31);
                unsigned old = atomicOr(&bm[s >> 5], bit);
                if (!(old & bit)) {
                    float4 z = make_float4(0.f, 0.f, 0.f, 0.f);
                    acc4[s * 2 + 0] = z;
                    acc4[s * 2 + 1] = z;
                    int p = atomicAdd(&g_ncnt[b], 1);
                    if (p < NODE_CAP) g_nodelist[b * NODE_CAP + p] = s;
                }
            }
        }
    }
}

// ---------------------------------------------------------------------------
// Scan: stream dst column; marked-dst edges do layer-0 attention into the
// global acc (vector REDs); output-node edges append to the layer-1 lists.
// ---------------------------------------------------------------------------
__global__ void __launch_bounds__(256) scan_kernel(
        const float* __restrict__ x,
        const int*   __restrict__ edge_index,
        const float* __restrict__ edge_time,
        const float* __restrict__ timestamp,
        const int*   __restrict__ src_index,
        const int*   __restrict__ dst_index,
        const float* __restrict__ time_w,
        const float* __restrict__ time_b,
        const float* __restrict__ Wq,
        const float* __restrict__ Wk,
        const float* __restrict__ Wv) {
    __shared__ unsigned sbm[64];
    int blk = blockIdx.x;
    int b = blk >> 3, chunk = blk & 7;
    if (threadIdx.x < 64) sbm[threadIdx.x] = g_bitmap[b * 64 + threadIdx.x];
    __syncthreads();

    int out0 = __ldg(src_index + b);
    int out1 = __ldg(dst_index + b);
    float ts = __ldg(timestamp + b);
    float tw[4], tb[4];
#pragma unroll
    for (int j = 0; j < 4; j++) { tw[j] = __ldg(time_w + j); tb[j] = __ldg(time_b + j); }

    const int* ei = edge_index + (size_t)b * 2 * E;
    const int* srcp = ei + chunk * CHUNK;
    const float* etp = edge_time + (size_t)b * E + chunk * CHUNK;
    const int4* dst4 = reinterpret_cast<const int4*>(ei + E + chunk * CHUNK);
    const float4* xb = reinterpret_cast<const float4*>(x) + b * N;
    float* accb = g_acc + (size_t)b * N * 8;

    for (int i = threadIdx.x; i < CHUNK / 4; i += 256) {
        int4 d = __ldg(dst4 + i);
        int dd[4] = {d.x, d.y, d.z, d.w};
#pragma unroll
        for (int u = 0; u < 4; u++) {
            int dstn = dd[u];
            if (!((sbm[dstn >> 5] >> (dstn & 31)) & 1u)) continue;
            int src = __ldg(srcp + i * 4 + u);
            float tv = __ldg(etp + i * 4 + u);

            // layer-1 edge lists (non-exclusive: handles out0 == out1)
            if (dstn == out0) {
                int p = atomicAdd(&g_cnt[b * 2 + 0], 1);
                if (p < LIST_CAP)
                    g_list[(size_t)(b * 2 + 0) * LIST_CAP + p] =
                        make_int2(src, __float_as_int(tv));
            }
            if (dstn == out1) {
                int p = atomicAdd(&g_cnt[b * 2 + 1], 1);
                if (p < LIST_CAP)
                    g_list[(size_t)(b * 2 + 1) * LIST_CAP + p] =
                        make_int2(src, __float_as_int(tv));
            }

            // layer-0 edge math (h0 = x)
            float dt = ts - tv;
            float4 hs = __ldg(xb + src);
            float msg[8];
            msg[0] = hs.x; msg[1] = hs.y; msg[2] = hs.z; msg[3] = hs.w;
#pragma unroll
            for (int j = 0; j < 4; j++) msg[4 + j] = __cosf(fmaf(dt, tw[j], tb[j]));

            float k[4];
#pragma unroll
            for (int j = 0; j < 4; j++) {
                float acc = msg[0] * __ldg(Wk + 0 * 4 + j);
#pragma unroll
                for (int r = 1; r < 8; r++) acc = fmaf(msg[r], __ldg(Wk + r * 4 + j), acc);
                k[j] = acc;
            }
            float4 hd = __ldg(xb + dstn);
            float q[4];
#pragma unroll
            for (int j = 0; j < 4; j++) {
                float a = hd.x * __ldg(Wq + 0 * 4 + j);
                a = fmaf(hd.y, __ldg(Wq + 1 * 4 + j), a);
                a = fmaf(hd.z, __ldg(Wq + 2 * 4 + j), a);
                a = fmaf(hd.w, __ldg(Wq + 3 * 4 + j), a);
                q[j] = a * INV_SQRT_DH;
            }
            float l0 = fmaf(q[0], k[0], q[1] * k[1]);
            float l1 = fmaf(q[2], k[2], q[3] * k[3]);
            float p0 = __expf(fminf(l0, 80.0f));
            float p1 = __expf(fminf(l1, 80.0f));

            float v[4];
#pragma unroll
            for (int j = 0; j < 4; j++) {
                float acc = msg[0] * __ldg(Wv + 0 * 4 + j);
#pragma unroll
                for (int r = 1; r < 8; r++) acc = fmaf(msg[r], __ldg(Wv + r * 4 + j), acc);
                v[j] = acc;
            }
            float* na = accb + dstn * 8;
            atomicAdd(reinterpret_cast<float4*>(na),
                      make_float4(p0 * v[0], p0 * v[1], p1 * v[2], p1 * v[3]));
            atomicAdd(reinterpret_cast<float2*>(na + 4), make_float2(p0, p1));
        }
    }
}

// ---------------------------------------------------------------------------
// Finalize: per batch, h1 for the ~34 listed nodes (one parallel load round),
// layer-1 over the listed edges, then the linear head.
// ---------------------------------------------------------------------------
__global__ void __launch_bounds__(256) final_kernel(
        const float* __restrict__ x,
        const float* __restrict__ timestamp,
        const int*   __restrict__ src_index,
        const int*   __restrict__ dst_index,
        const float* __restrict__ time_w,
        const float* __restrict__ time_b,
        const float* __restrict__ Wq,
        const float* __restrict__ Wk,
        const float* __restrict__ Wv,
        const float* __restrict__ Wo,
        const float* __restrict__ bo,
        const float* __restrict__ W_lin,
        const float* __restrict__ b_lin,
        float* __restrict__ out) {
    __shared__ float4 sh1[N];        // 32 KB; only listed entries are written/read
    __shared__ float sacc[12];

    int b = blockIdx.x, t = threadIdx.x;
    if (t < 12) sacc[t] = 0.0f;

    const float4* xb = reinterpret_cast<const float4*>(x) + b * N;
    const float* accb = g_acc + (size_t)b * N * 8;
    float ts = __ldg(timestamp + b);
    float tw[4], tb[4];
#pragma unroll
    for (int j = 0; j < 4; j++) { tw[j] = __ldg(time_w + j); tb[j] = __ldg(time_b + j); }

    // h1 for listed nodes: one node per thread, one parallel load round.
    int nmarked = min(__ldg(&g_ncnt[b]), NODE_CAP);
    if (t < nmarked) {
        int n = g_nodelist[b * NODE_CAP + t];
        const float4* na4 = reinterpret_cast<const float4*>(accb) + n * 2;
        float4 agg = __ldg(na4 + 0);
        float4 sv  = __ldg(na4 + 1);
        float s0 = sv.x, s1 = sv.y;
        float r0 = (s0 == 0.0f) ? 1.0f : __frcp_rn(s0);
        float r1 = (s1 == 0.0f) ? 1.0f : __frcp_rn(s1);
        float at0 = agg.x * r0, at1 = agg.y * r0;
        float at2 = agg.z * r1, at3 = agg.w * r1;
        float4 xv = __ldg(xb + n);
        float hin[4] = {xv.x, xv.y, xv.z, xv.w};
        float h1[4];
#pragma unroll
        for (int j = 0; j < 4; j++) {
            float vv = hin[j] + __ldg(bo + j);
            vv = fmaf(at0, __ldg(Wo + 0 * 4 + j), vv);
            vv = fmaf(at1, __ldg(Wo + 1 * 4 + j), vv);
            vv = fmaf(at2, __ldg(Wo + 2 * 4 + j), vv);
            vv = fmaf(at3, __ldg(Wo + 3 * 4 + j), vv);
            h1[j] = fmaxf(vv, 0.0f);
        }
        sh1[n] = make_float4(h1[0], h1[1], h1[2], h1[3]);
    }
    __syncthreads();

    int out0 = __ldg(src_index + b);
    int out1 = __ldg(dst_index + b);
    int cnt0 = min(g_cnt[b * 2 + 0], LIST_CAP);
    int cnt1 = min(g_cnt[b * 2 + 1], LIST_CAP);
    const float* WkL = Wk + 32;
    const float* WvL = Wv + 32;
    const float* WqL = Wq + 16;

    for (int j = t; j < cnt0 + cnt1; j += 256) {
        int which = (j < cnt0) ? 0 : 1;
        int2 pl = g_list[(size_t)(b * 2 + which) * LIST_CAP +
                         (which == 0 ? j : j - cnt0)];
        int outn = (which == 0) ? out0 : out1;

        float dt = ts - __int_as_float(pl.y);
        float4 hs = sh1[pl.x];
        float msg[8];
        msg[0] = hs.x; msg[1] = hs.y; msg[2] = hs.z; msg[3] = hs.w;
#pragma unroll
        for (int r = 0; r < 4; r++) msg[4 + r] = __cosf(fmaf(dt, tw[r], tb[r]));

        float k[4];
#pragma unroll
        for (int c = 0; c < 4; c++) {
            float acc = msg[0] * __ldg(WkL + 0 * 4 + c);
#pragma unroll
            for (int r = 1; r < 8; r++) acc = fmaf(msg[r], __ldg(WkL + r * 4 + c), acc);
            k[c] = acc;
        }
        float4 hd = sh1[outn];
        float q[4];
#pragma unroll
        for (int c = 0; c < 4; c++) {
            float a = hd.x * __ldg(WqL + 0 * 4 + c);
            a = fmaf(hd.y, __ldg(WqL + 1 * 4 + c), a);
            a = fmaf(hd.z, __ldg(WqL + 2 * 4 + c), a);
            a = fmaf(hd.w, __ldg(WqL + 3 * 4 + c), a);
            q[c] = a * INV_SQRT_DH;
        }
        float l0 = fmaf(q[0], k[0], q[1] * k[1]);
        float l1 = fmaf(q[2], k[2], q[3] * k[3]);
        float p0 = __expf(fminf(l0, 80.0f));
        float p1 = __expf(fminf(l1, 80.0f));

        float v[4];
#pragma unroll
        for (int c = 0; c < 4; c++) {
            float acc = msg[0] * __ldg(WvL + 0 * 4 + c);
#pragma unroll
            for (int r = 1; r < 8; r++) acc = fmaf(msg[r], __ldg(WvL + r * 4 + c), acc);
            v[c] = acc;
        }
        float* na = sacc + which * 6;
        atomicAdd(na + 0, p0);
        atomicAdd(na + 1, p1);
        atomicAdd(na + 2, p0 * v[0]);
        atomicAdd(na + 3, p0 * v[1]);
        atomicAdd(na + 4, p1 * v[2]);
        atomicAdd(na + 5, p1 * v[3]);
    }
    __syncthreads();

    if (t == 0) {
        float f[12];
        const float* WoL = Wo + 16;
        const float* boL = bo + 4;
#pragma unroll
        for (int w = 0; w < 2; w++) {
            int outn = (w == 0) ? out0 : out1;
            const float* na = sacc + w * 6;
            float s0 = na[0], s1 = na[1];
            float r0 = (s0 == 0.0f) ? 1.0f : __frcp_rn(s0);
            float r1 = (s1 == 0.0f) ? 1.0f : __frcp_rn(s1);
            float at0 = na[2] * r0, at1 = na[3] * r0;
            float at2 = na[4] * r1, at3 = na[5] * r1;
            float4 h1v = sh1[outn];
            float hin[4] = {h1v.x, h1v.y, h1v.z, h1v.w};
#pragma unroll
            for (int j = 0; j < 4; j++) {
                float vv = hin[j] + __ldg(boL + j);
                vv = fmaf(at0, __ldg(WoL + 0 * 4 + j), vv);
                vv = fmaf(at1, __ldg(WoL + 1 * 4 + j), vv);
                vv = fmaf(at2, __ldg(WoL + 2 * 4 + j), vv);
                vv = fmaf(at3, __ldg(WoL + 3 * 4 + j), vv);
                f[w * 4 + j] = fmaxf(vv, 0.0f);
            }
        }
#pragma unroll
        for (int j = 0; j < 4; j++) f[8 + j] = cosf(fmaf(ts, tw[j], tb[j]));
#pragma unroll
        for (int c = 0; c < 2; c++) {
            float acc = __ldg(b_lin + c);
#pragma unroll
            for (int i = 0; i < 12; i++) acc = fmaf(f[i], __ldg(W_lin + i * 2 + c), acc);
            out[b * 2 + c] = acc;
        }
    }
}

} // anonymous namespace

extern "C" void kernel_launch(void* const* d_in, const int* in_sizes, int n_in,
                              void* d_out, int out_size) {
    const float* x          = (const float*)d_in[0];
    const int*   edge_index = (const int*)  d_in[1];
    const float* edge_time  = (const float*)d_in[2];
    const float* timestamp  = (const float*)d_in[3];
    const int*   src_index  = (const int*)  d_in[4];
    const int*   dst_index  = (const int*)  d_in[5];
    const float* time_w     = (const float*)d_in[6];
    const float* time_b     = (const float*)d_in[7];
    const float* Wq         = (const float*)d_in[8];
    const float* Wk         = (const float*)d_in[9];
    const float* Wv         = (const float*)d_in[10];
    const float* Wo         = (const float*)d_in[11];
    const float* bo         = (const float*)d_in[12];
    const float* W_lin      = (const float*)d_in[13];
    const float* b_lin      = (const float*)d_in[14];
    float* out = (float*)d_out;

    zero_kernel<<<B, 64>>>(src_index, dst_index);
    mark_kernel<<<B * SPLIT, 256>>>(edge_index, src_index, dst_index);
    scan_kernel<<<B * SPLIT, 256>>>(x, edge_index, edge_time, timestamp,
                                    src_index, dst_index,
                                    time_w, time_b, Wq, Wk, Wv);
    final_kernel<<<B, 256>>>(x, timestamp, src_index, dst_index,
                             time_w, time_b, Wq, Wk, Wv, Wo, bo,
                             W_lin, b_lin, out);
}